// round 3
// baseline (speedup 1.0000x reference)
#include <cuda_runtime.h>
#include <math.h>

// Scratch: pooled features [B, 192]  (ligand -> [0,96), protein -> [96,192))
#define BATCH 4096
__device__ float g_feat[BATCH * 192];

typedef unsigned long long u64;

// packed fp32x2 FMA: d = a*b + d  (Blackwell full-width FP32 path)
__device__ __forceinline__ void ffma2(u64& d, u64 a, u64 b)
{
    asm("fma.rn.f32x2 %0, %1, %2, %0;" : "+l"(d) : "l"(a), "l"(b));
}
// pack {x, x} into a 64-bit lane pair
__device__ __forceinline__ u64 dup2(float x)
{
    u64 r;
    asm("mov.b64 %0, {%1, %1};" : "=l"(r) : "f"(x));
    return r;
}

// ---------------------------------------------------------------------------
// Fused conv1d(valid) + bias + ReLU + global max pool.
// One CTA per sample. Input row and transposed weights staged in dynamic smem.
// Each thread owns an 8(channel) x 8(position) accumulator tile kept as
// 4x8 packed f32x2 pairs (pairs along the channel dim, so float4 weight loads
// provide packed operands for free; x is broadcast-duplicated once per row).
// ---------------------------------------------------------------------------
template <int VOCAB, int LEN, int K, int LENP, int FEAT_OFF>
__global__ __launch_bounds__(256, 1)
void conv_branch_kernel(const float* __restrict__ x,
                        const float* __restrict__ w,
                        const float* __restrict__ bias)
{
    constexpr int CH  = 96;
    constexpr int OUT = LEN - K + 1;
    constexpr int NT  = (OUT + 7) / 8;      // t-tiles
    constexpr int NC  = CH / 8;             // c-tiles = 12
    constexpr int XW  = 8 + K - 1;          // x-window width actually used

    extern __shared__ float smem[];
    float* s_x = smem;                        // VOCAB * LENP
    float* s_w = s_x + VOCAB * LENP;          // (VOCAB*K) x CH  (transposed)
    float* s_b = s_w + VOCAB * K * CH;        // CH
    float* s_m = s_b + CH;                    // CH  (running max, >= 0)

    const int b   = blockIdx.x;
    const int tid = threadIdx.x;

    // ---- stage input (vectorized; LEN % 4 == 0 so float4s never cross rows)
    const float4* xg = reinterpret_cast<const float4*>(x + (size_t)b * VOCAB * LEN);
    for (int u = tid; u < VOCAB * LEN / 4; u += 256) {
        float4 v4 = xg[u];
        int flat = 4 * u;
        int v = flat / LEN;
        int t = flat - v * LEN;
        *reinterpret_cast<float4*>(&s_x[v * LENP + t]) = v4;
    }
    // zero the pad columns (read by the last tile's halo, masked in epilogue)
    for (int u = tid; u < VOCAB * (LENP - LEN); u += 256) {
        int v = u / (LENP - LEN);
        int t = LEN + (u - v * (LENP - LEN));
        s_x[v * LENP + t] = 0.f;
    }
    // ---- stage weights transposed: s_w[(v*K+k)*CH + c] = w[c, v, k]
    for (int f = tid; f < CH * VOCAB * K; f += 256) {
        int c  = f / (VOCAB * K);
        int vk = f - c * (VOCAB * K);
        s_w[vk * CH + c] = w[f];
    }
    if (tid < CH) { s_b[tid] = bias[tid]; s_m[tid] = 0.f; }
    __syncthreads();

    for (int tile = tid; tile < NC * NT; tile += 256) {
        int ct = tile / NT;
        int tt = tile - ct * NT;
        int c0 = ct * 8, t0 = tt * 8;

        // acc2[p][j]: channel pair (c0+2p, c0+2p+1) at position t0+j
        u64 acc2[4][8];
        #pragma unroll
        for (int p = 0; p < 4; p++)
            #pragma unroll
            for (int j = 0; j < 8; j++) acc2[p][j] = 0ull;

        #pragma unroll 1
        for (int v = 0; v < VOCAB; v++) {
            // x window as packed duplicates {x,x}
            float xr[16];
            const float4* xp = reinterpret_cast<const float4*>(&s_x[v * LENP + t0]);
            #pragma unroll
            for (int q = 0; q < 4; q++) {
                float4 t4 = xp[q];
                xr[4*q+0] = t4.x; xr[4*q+1] = t4.y;
                xr[4*q+2] = t4.z; xr[4*q+3] = t4.w;
            }
            u64 xx[XW];
            #pragma unroll
            for (int m = 0; m < XW; m++) xx[m] = dup2(xr[m]);

            #pragma unroll
            for (int k = 0; k < K; k++) {
                const u64* wp =
                    reinterpret_cast<const u64*>(&s_w[(v * K + k) * CH + c0]);
                u64 w2[4];
                #pragma unroll
                for (int p = 0; p < 4; p++) w2[p] = wp[p];
                #pragma unroll
                for (int p = 0; p < 4; p++)
                    #pragma unroll
                    for (int j = 0; j < 8; j++)
                        ffma2(acc2[p][j], w2[p], xx[j + k]);
            }
        }

        // bias + ReLU + local max (m starts at 0 == ReLU floor), masked tail
        #pragma unroll
        for (int p = 0; p < 4; p++) {
            float2 bb = *reinterpret_cast<const float2*>(&s_b[c0 + 2 * p]);
            float mlo = 0.f, mhi = 0.f;
            #pragma unroll
            for (int j = 0; j < 8; j++) {
                if (t0 + j < OUT) {
                    float2 a = *reinterpret_cast<const float2*>(&acc2[p][j]);
                    mlo = fmaxf(mlo, a.x + bb.x);
                    mhi = fmaxf(mhi, a.y + bb.y);
                }
            }
            // nonneg floats: int-bit compare is order-preserving
            atomicMax(reinterpret_cast<int*>(&s_m[c0 + 2 * p]),     __float_as_int(mlo));
            atomicMax(reinterpret_cast<int*>(&s_m[c0 + 2 * p + 1]), __float_as_int(mhi));
        }
    }
    __syncthreads();
    if (tid < CH) g_feat[(size_t)b * 192 + FEAT_OFF + tid] = s_m[tid];
}

// ---------------------------------------------------------------------------
// Per-sample: x = feat.reshape(6,32); gram = x^T x; L2-normalize; dot w_aff.
// One warp per sample; lane owns Gram column k=lane.
// ---------------------------------------------------------------------------
__global__ __launch_bounds__(256)
void gram_readout_kernel(const float* __restrict__ w_aff,
                         const float* __restrict__ b_aff,
                         float* __restrict__ out, int B)
{
    __shared__ float s_w[1024];
    __shared__ float s_f[8][192];
    const int tid  = threadIdx.x;
    const int warp = tid >> 5, lane = tid & 31;
    const int b = blockIdx.x * 8 + warp;

    for (int u = tid; u < 1024; u += 256) s_w[u] = w_aff[u];
    if (b < B)
        for (int u = lane; u < 192; u += 32) s_f[warp][u] = g_feat[(size_t)b * 192 + u];
    __syncthreads();
    if (b >= B) return;

    float xk[6];
    #pragma unroll
    for (int i = 0; i < 6; i++) xk[i] = s_f[warp][i * 32 + lane];

    float s1 = 0.f, s2 = 0.f;
    #pragma unroll 4
    for (int j = 0; j < 32; j++) {
        float g = 0.f;
        #pragma unroll
        for (int i = 0; i < 6; i++) g = fmaf(s_f[warp][i * 32 + j], xk[i], g);
        s2 = fmaf(g, g, s2);
        s1 = fmaf(g, s_w[j * 32 + lane], s1);
    }
    #pragma unroll
    for (int off = 16; off > 0; off >>= 1) {
        s1 += __shfl_xor_sync(0xffffffffu, s1, off);
        s2 += __shfl_xor_sync(0xffffffffu, s2, off);
    }
    if (lane == 0) out[b] = s1 / (sqrtf(s2) + 1e-12f) + b_aff[0];
}

// ---------------------------------------------------------------------------

extern "C" void kernel_launch(void* const* d_in, const int* in_sizes, int n_in,
                              void* d_out, int out_size)
{
    // positional defaults per metadata order
    const float* protein = (const float*)d_in[0];
    const float* ligand  = (const float*)d_in[1];
    const float* w_pro   = (const float*)d_in[2];
    const float* b_pro   = (const float*)d_in[3];
    const float* w_lig   = (const float*)d_in[4];
    const float* b_lig   = (const float*)d_in[5];
    const float* w_aff   = (const float*)d_in[6];
    const float* b_aff   = (const float*)d_in[7];

    // defensive: resolve by element count (all distinct except the two biases,
    // which keep their relative order)
    int seen96 = 0;
    for (int i = 0; i < n_in; i++) {
        long long s = in_sizes[i];
        const float* p = (const float*)d_in[i];
        if      (s == (long long)BATCH * 25 * 1000) protein = p;
        else if (s == (long long)BATCH * 64 * 100)  ligand  = p;
        else if (s == 96LL * 25 * 8)                w_pro   = p;
        else if (s == 96LL * 64 * 4)                w_lig   = p;
        else if (s == 1024LL)                       w_aff   = p;
        else if (s == 96LL) { if (seen96++ == 0) b_pro = p; else b_lig = p; }
        else if (s == 1LL)                          b_aff   = p;
    }

    float* out = (float*)d_out;

    constexpr int PRO_SMEM = (25 * 1008 + 25 * 8 * 96 + 96 + 96) * 4;  // 178368
    constexpr int LIG_SMEM = (64 * 112  + 64 * 4 * 96 + 96 + 96) * 4;  // 127744

    cudaFuncSetAttribute(conv_branch_kernel<25, 1000, 8, 1008, 96>,
                         cudaFuncAttributeMaxDynamicSharedMemorySize, PRO_SMEM);
    cudaFuncSetAttribute(conv_branch_kernel<64, 100, 4, 112, 0>,
                         cudaFuncAttributeMaxDynamicSharedMemorySize, LIG_SMEM);

    conv_branch_kernel<64, 100, 4, 112, 0><<<BATCH, 256, LIG_SMEM>>>(ligand, w_lig, b_lig);
    conv_branch_kernel<25, 1000, 8, 1008, 96><<<BATCH, 256, PRO_SMEM>>>(protein, w_pro, b_pro);
    gram_readout_kernel<<<BATCH / 8, 256>>>(w_aff, b_aff, out, BATCH);
}

// round 5
// speedup vs baseline: 2.2476x; 2.2476x over previous
#include <cuda_runtime.h>
#include <cuda_bf16.h>
#include <math.h>

#define BATCH 4096
__device__ float g_feat[BATCH * 192];
// prepped weights: [c][k_lin], k_lin = tap*VPAD + v, 96 x 256 each branch
__device__ __nv_bfloat16 g_whL[96 * 256], g_wlL[96 * 256];   // ligand
__device__ __nv_bfloat16 g_whP[96 * 256], g_wlP[96 * 256];   // protein

typedef unsigned int u32;

__device__ __forceinline__ u32 sm32(const void* p) {
    u32 a;
    asm("{ .reg .u64 t; cvta.to.shared.u64 t, %1; cvt.u32.u64 %0, t; }"
        : "=r"(a) : "l"(p));
    return a;
}
__device__ __forceinline__ void ldsm4(u32& r0, u32& r1, u32& r2, u32& r3, u32 a) {
    asm volatile("ldmatrix.sync.aligned.m8n8.x4.shared.b16 {%0,%1,%2,%3}, [%4];"
                 : "=r"(r0), "=r"(r1), "=r"(r2), "=r"(r3) : "r"(a));
}
__device__ __forceinline__ void mma16816(float* d, u32 a0, u32 a1, u32 a2, u32 a3,
                                         u32 b0, u32 b1) {
    asm volatile(
        "mma.sync.aligned.m16n8k16.row.col.f32.bf16.bf16.f32 "
        "{%0,%1,%2,%3}, {%4,%5,%6,%7}, {%8,%9}, {%0,%1,%2,%3};"
        : "+f"(d[0]), "+f"(d[1]), "+f"(d[2]), "+f"(d[3])
        : "r"(a0), "r"(a1), "r"(a2), "r"(a3), "r"(b0), "r"(b1));
}

// ---------------------------------------------------------------------------
// weight prep: fp32 [96][VU][TAPS] -> bf16 hi/lo [96][256] with k_lin=tap*VPAD+v
// ---------------------------------------------------------------------------
template <int VU, int TAPS, int VPAD, bool PRO>
__global__ void prep_w(const float* __restrict__ w) {
    int u = blockIdx.x * 256 + threadIdx.x;
    if (u >= 96 * 256) return;
    int c = u >> 8, k = u & 255;
    int tap = k / VPAD, v = k - tap * VPAD;
    float val = (v < VU) ? w[(c * VU + v) * TAPS + tap] : 0.f;
    __nv_bfloat16 hi = __float2bfloat16(val);
    __nv_bfloat16 lo = __float2bfloat16(val - __bfloat162float(hi));
    if (PRO) { g_whP[u] = hi; g_wlP[u] = lo; }
    else     { g_whL[u] = hi; g_wlL[u] = lo; }
}

__global__ void zero_feat_kernel() {
    int i = blockIdx.x * 1024 + threadIdx.x;
    if (i < BATCH * 192) g_feat[i] = 0.f;
}

// ---------------------------------------------------------------------------
// Persistent conv kernel via mma.sync m16n8k16 bf16 (3-way hi/lo split).
//   Tile = 128 output positions x 96 channels. Warp wid owns positions
//   [wid*16, wid*16+16). A = x time-major rows (stride XSTR bytes, pad rows
//   conflict-free mod 128); tap shift = +tap rows on the A descriptor.
//   B = weights [ch][k] rows (stride 528). Epilogue: register max ->
//   shfl reduce -> global atomicMax (fused bias+ReLU+maxpool).
// ---------------------------------------------------------------------------
template <int VU, int VPAD, int CHK, int TAPS, int LEN, int OUT, int NTPER,
          int FEAT_OFF, int XSTR, bool PRO>
__global__ __launch_bounds__(256, 1)
void conv_mma(const float* __restrict__ x, const float* __restrict__ bias)
{
    constexpr int WSTR  = 528;               // 96 rows x 256 bf16 (+16B pad)
    constexpr int ROWS  = 136;               // x rows per buffer (>= 131 halo)
    constexpr int WHALF = 96 * WSTR;
    constexpr int OFF_W = 0;                 // [hi][lo]
    constexpr int OFF_X = 2 * WHALF;         // 101376
    constexpr int XHALF = ROWS * XSTR;
    constexpr int XBUF  = 2 * XHALF;         // hi+lo per buffer
    constexpr int OFF_B = OFF_X + 2 * XBUF;  // bias (96 floats)
    constexpr int NTILES = BATCH * NTPER;
    constexpr int NLD   = (VU * ROWS + 255) / 256;

    extern __shared__ char sm[];
    const u32 sb  = sm32(sm);
    const int tid = threadIdx.x, wid = tid >> 5, lane = tid & 31;

    const __nv_bfloat16* wh = PRO ? g_whP : g_whL;
    const __nv_bfloat16* wl = PRO ? g_wlP : g_wlL;

    // stage weights (hi/lo) into padded rows
    for (int u = tid; u < 96 * 256; u += 256) {
        int c = u >> 8, k = u & 255;
        *(__nv_bfloat16*)(sm + OFF_W + c * WSTR + k * 2)         = wh[u];
        *(__nv_bfloat16*)(sm + OFF_W + WHALF + c * WSTR + k * 2) = wl[u];
    }
    // zero entire x region once (covers vocab pad columns + row pads)
    for (int u = tid; u < (2 * XBUF) / 16; u += 256)
        *reinterpret_cast<float4*>(sm + OFF_X + u * 16) =
            make_float4(0.f, 0.f, 0.f, 0.f);
    if (tid < 96) *(float*)(sm + OFF_B + tid * 4) = bias[tid];
    __syncthreads();

    auto load_regs = [&](int g, float* xr) {
        int b = g / NTPER, tt = g - b * NTPER, t0 = tt * 128;
        int valid = LEN - t0; if (valid > ROWS) valid = ROWS;
        const float* xb = x + (size_t)b * VU * LEN + t0;
        #pragma unroll
        for (int i = 0; i < NLD; i++) {
            int u = tid + i * 256;
            float v = 0.f;
            if (u < VU * ROWS) {
                int vv = u / ROWS, r = u - vv * ROWS;
                if (r < valid) v = xb[vv * LEN + r];
            }
            xr[i] = v;
        }
    };
    auto store_smem = [&](int buf, const float* xr) {
        #pragma unroll
        for (int i = 0; i < NLD; i++) {
            int u = tid + i * 256;
            if (u < VU * ROWS) {
                int vv = u / ROWS, r = u - vv * ROWS;
                float val = xr[i];
                __nv_bfloat16 hi = __float2bfloat16(val);
                __nv_bfloat16 lo = __float2bfloat16(val - __bfloat162float(hi));
                char* p = sm + OFF_X + buf * XBUF + r * XSTR + vv * 2;
                *(__nv_bfloat16*)p = hi;
                *(__nv_bfloat16*)(p + XHALF) = lo;
            }
        }
    };

    // ldmatrix lane-offsets (derived from m16n8k16 fragment mappings)
    const u32 a_lo = (u32)((lane & 15) * XSTR + (lane >> 4) * 16);
    const u32 b_lo = (u32)(((lane & 7) + ((lane >> 4) << 3)) * WSTR
                           + ((lane >> 3) & 1) * 16);

    const int g0 = blockIdx.x;
    float xr[NLD];
    if (g0 < NTILES) { load_regs(g0, xr); store_smem(0, xr); }
    __syncthreads();

    int buf = 0;
    for (int g = g0; g < NTILES; g += gridDim.x) {
        const int gn = g + (int)gridDim.x;
        if (gn < NTILES) load_regs(gn, xr);   // LDGs overlap the mma loop

        float acc[12][4];
        #pragma unroll
        for (int j = 0; j < 12; j++)
            #pragma unroll
            for (int e = 0; e < 4; e++) acc[j][e] = 0.f;

        const u32 xh = sb + OFF_X + buf * XBUF + (u32)(wid * 16) * XSTR + a_lo;
        const u32 xl = xh + XHALF;
        const u32 wbh = sb + OFF_W + b_lo;
        const u32 wbl = wbh + WHALF;

        #pragma unroll
        for (int tap = 0; tap < TAPS; tap++) {
            #pragma unroll
            for (int ch = 0; ch < CHK; ch++) {
                const u32 aoff = (u32)(tap * XSTR + ch * 32);
                u32 ah0, ah1, ah2, ah3, al0, al1, al2, al3;
                ldsm4(ah0, ah1, ah2, ah3, xh + aoff);
                ldsm4(al0, al1, al2, al3, xl + aoff);
                const u32 wk = (u32)((tap * VPAD + ch * 16) * 2);
                #pragma unroll
                for (int p = 0; p < 6; p++) {
                    u32 bh0, bh1, bh2, bh3, bl0, bl1, bl2, bl3;
                    ldsm4(bh0, bh1, bh2, bh3, wbh + (u32)(p * 16 * WSTR) + wk);
                    ldsm4(bl0, bl1, bl2, bl3, wbl + (u32)(p * 16 * WSTR) + wk);
                    // hi*hi
                    mma16816(acc[2 * p],     ah0, ah1, ah2, ah3, bh0, bh1);
                    mma16816(acc[2 * p + 1], ah0, ah1, ah2, ah3, bh2, bh3);
                    // hi*lo
                    mma16816(acc[2 * p],     ah0, ah1, ah2, ah3, bl0, bl1);
                    mma16816(acc[2 * p + 1], ah0, ah1, ah2, ah3, bl2, bl3);
                    // lo*hi
                    mma16816(acc[2 * p],     al0, al1, al2, al3, bh0, bh1);
                    mma16816(acc[2 * p + 1], al0, al1, al2, al3, bh2, bh3);
                }
            }
        }

        // store next tile into the other buffer (readers of it sync below)
        if (gn < NTILES) store_smem(buf ^ 1, xr);

        // ---- epilogue: positions m = t0 + wid*16 + lane/4 (+8)
        {
            const int b  = g / NTPER;
            const int t0 = (g - b * NTPER) * 128;
            const int pos = t0 + wid * 16 + (lane >> 2);
            const float NEG = -1e30f;
            const bool v0 = pos < OUT, v1 = pos + 8 < OUT;
            float mx[24];
            #pragma unroll
            for (int j = 0; j < 12; j++) {
                mx[2 * j]     = fmaxf(v0 ? acc[j][0] : NEG, v1 ? acc[j][2] : NEG);
                mx[2 * j + 1] = fmaxf(v0 ? acc[j][1] : NEG, v1 ? acc[j][3] : NEG);
            }
            #pragma unroll
            for (int off = 4; off <= 16; off <<= 1)
                #pragma unroll
                for (int q = 0; q < 24; q++)
                    mx[q] = fmaxf(mx[q], __shfl_xor_sync(0xffffffffu, mx[q], off));
            if (lane < 4) {
                #pragma unroll
                for (int j = 0; j < 12; j++)
                    #pragma unroll
                    for (int e = 0; e < 2; e++) {
                        int c = j * 8 + lane * 2 + e;
                        float bb = *(const float*)(sm + OFF_B + c * 4);
                        float val = fmaxf(mx[2 * j + e] + bb, 0.f);
                        atomicMax(reinterpret_cast<int*>(
                                      &g_feat[(size_t)b * 192 + FEAT_OFF + c]),
                                  __float_as_int(val));
                    }
            }
        }
        __syncthreads();
        buf ^= 1;
    }
}

// ---------------------------------------------------------------------------
// Per-sample: x = feat.reshape(6,32); gram = x^T x; L2-normalize; dot w_aff.
// ---------------------------------------------------------------------------
__global__ __launch_bounds__(256)
void gram_readout_kernel(const float* __restrict__ w_aff,
                         const float* __restrict__ b_aff,
                         float* __restrict__ out, int B)
{
    __shared__ float s_w[1024];
    __shared__ float s_f[8][192];
    const int tid  = threadIdx.x;
    const int warp = tid >> 5, lane = tid & 31;
    const int b = blockIdx.x * 8 + warp;

    for (int u = tid; u < 1024; u += 256) s_w[u] = w_aff[u];
    if (b < B)
        for (int u = lane; u < 192; u += 32) s_f[warp][u] = g_feat[(size_t)b * 192 + u];
    __syncthreads();
    if (b >= B) return;

    float xk[6];
    #pragma unroll
    for (int i = 0; i < 6; i++) xk[i] = s_f[warp][i * 32 + lane];

    float s1 = 0.f, s2 = 0.f;
    #pragma unroll 4
    for (int j = 0; j < 32; j++) {
        float g = 0.f;
        #pragma unroll
        for (int i = 0; i < 6; i++) g = fmaf(s_f[warp][i * 32 + j], xk[i], g);
        s2 = fmaf(g, g, s2);
        s1 = fmaf(g, s_w[j * 32 + lane], s1);
    }
    #pragma unroll
    for (int off = 16; off > 0; off >>= 1) {
        s1 += __shfl_xor_sync(0xffffffffu, s1, off);
        s2 += __shfl_xor_sync(0xffffffffu, s2, off);
    }
    if (lane == 0) out[b] = s1 / (sqrtf(s2) + 1e-12f) + b_aff[0];
}

// ---------------------------------------------------------------------------

extern "C" void kernel_launch(void* const* d_in, const int* in_sizes, int n_in,
                              void* d_out, int out_size)
{
    const float* protein = (const float*)d_in[0];
    const float* ligand  = (const float*)d_in[1];
    const float* w_pro   = (const float*)d_in[2];
    const float* b_pro   = (const float*)d_in[3];
    const float* w_lig   = (const float*)d_in[4];
    const float* b_lig   = (const float*)d_in[5];
    const float* w_aff   = (const float*)d_in[6];
    const float* b_aff   = (const float*)d_in[7];

    int seen96 = 0;
    for (int i = 0; i < n_in; i++) {
        long long s = in_sizes[i];
        const float* p = (const float*)d_in[i];
        if      (s == (long long)BATCH * 25 * 1000) protein = p;
        else if (s == (long long)BATCH * 64 * 100)  ligand  = p;
        else if (s == 96LL * 25 * 8)                w_pro   = p;
        else if (s == 96LL * 64 * 4)                w_lig   = p;
        else if (s == 1024LL)                       w_aff   = p;
        else if (s == 96LL) { if (seen96++ == 0) b_pro = p; else b_lig = p; }
        else if (s == 1LL)                          b_aff   = p;
    }

    float* out = (float*)d_out;

    // ligand : VU=64 VPAD=64 CHK=4 TAPS=4 LEN=100  OUT=97  NTPER=1 off=0  XSTR=144
    // protein: VU=25 VPAD=32 CHK=2 TAPS=8 LEN=1000 OUT=993 NTPER=8 off=96 XSTR=80
    constexpr int SMEM_L = 2 * 96 * 528 + 4 * 136 * 144 + 512;  // 180224-ish
    constexpr int SMEM_P = 2 * 96 * 528 + 4 * 136 * 80 + 512;

    auto kL = conv_mma<64, 64, 4, 4, 100, 97, 1, 0, 144, false>;
    auto kP = conv_mma<25, 32, 2, 8, 1000, 993, 8, 96, 80, true>;
    static bool attr_done = false;
    if (!attr_done) {
        cudaFuncSetAttribute(kL, cudaFuncAttributeMaxDynamicSharedMemorySize, SMEM_L);
        cudaFuncSetAttribute(kP, cudaFuncAttributeMaxDynamicSharedMemorySize, SMEM_P);
        attr_done = true;
    }

    zero_feat_kernel<<<(BATCH * 192 + 1023) / 1024, 1024>>>();
    prep_w<64, 4, 64, false><<<96, 256>>>(w_lig);
    prep_w<25, 8, 32, true><<<96, 256>>>(w_pro);
    kL<<<148, 256, SMEM_L>>>(ligand, b_lig);
    kP<<<148, 256, SMEM_P>>>(protein, b_pro);
    gram_readout_kernel<<<BATCH / 8, 256>>>(w_aff, b_aff, out, BATCH);
}

// round 7
// speedup vs baseline: 3.3967x; 1.5113x over previous
#include <cuda_runtime.h>
#include <cuda_fp16.h>
#include <math.h>

#define BATCH 4096
__device__ float g_feat[BATCH * 192];
// prepped fp16 weights: [c][k_lin], k_lin = tap*VPAD + v  (96 x 256 each)
__device__ __half g_wP[96 * 256], g_wL[96 * 256];

typedef unsigned int u32;

__device__ __forceinline__ u32 sm32(const void* p) {
    u32 a;
    asm("{ .reg .u64 t; cvta.to.shared.u64 t, %1; cvt.u32.u64 %0, t; }"
        : "=r"(a) : "l"(p));
    return a;
}
__device__ __forceinline__ void ldsm4(u32* r, u32 a) {
    asm volatile("ldmatrix.sync.aligned.m8n8.x4.shared.b16 {%0,%1,%2,%3}, [%4];"
                 : "=r"(r[0]), "=r"(r[1]), "=r"(r[2]), "=r"(r[3]) : "r"(a));
}
__device__ __forceinline__ void mma16816(float* d, const u32* a, u32 b0, u32 b1) {
    asm volatile(
        "mma.sync.aligned.m16n8k16.row.col.f32.f16.f16.f32 "
        "{%0,%1,%2,%3}, {%4,%5,%6,%7}, {%8,%9}, {%0,%1,%2,%3};"
        : "+f"(d[0]), "+f"(d[1]), "+f"(d[2]), "+f"(d[3])
        : "r"(a[0]), "r"(a[1]), "r"(a[2]), "r"(a[3]), "r"(b0), "r"(b1));
}
__device__ __forceinline__ void cp16(u32 dst, const void* src) {
    asm volatile("cp.async.ca.shared.global [%0], [%1], 16;" :: "r"(dst), "l"(src));
}
__device__ __forceinline__ void cp_commit() {
    asm volatile("cp.async.commit_group;" ::: "memory");
}
__device__ __forceinline__ void cp_wait0() {
    asm volatile("cp.async.wait_group 0;" ::: "memory");
}

// ---------------------------------------------------------------------------
// weight prep: fp32 [96][VU][TAPS] -> fp16 [96][256], k_lin = tap*VPAD + v
// ---------------------------------------------------------------------------
template <int VU, int TAPS, int VPAD, bool PRO>
__global__ void prep_w(const float* __restrict__ w) {
    int u = blockIdx.x * 256 + threadIdx.x;
    if (u >= 96 * 256) return;
    int c = u >> 8, k = u & 255;
    int tap = k / VPAD, v = k - tap * VPAD;
    float val = (v < VU) ? w[(c * VU + v) * TAPS + tap] : 0.f;
    (PRO ? g_wP : g_wL)[u] = __float2half_rn(val);
}

__global__ void zero_feat_kernel() {
    int i = blockIdx.x * 1024 + threadIdx.x;
    if (i < BATCH * 192) g_feat[i] = 0.f;
}

// ---------------------------------------------------------------------------
// Persistent conv via mma.sync m16n8k16 fp16 (x split hi/lo, w plain fp16):
//   acc += xh*w ; acc += xl*w   (== x*w up to w's fp16 quantization)
// Tile = TILE positions x 96 ch. Warp owns MW m16-frags (16*MW positions).
// x staged time-major rows (XSTR bytes, conflict-free mod 128); tap shift =
// +tap rows on the A address. cp.async stages next tile's fp32 into scratch
// during the mma loop; cvt->fp16 hi/lo happens between tiles.
// ---------------------------------------------------------------------------
template <int VU, int VPAD, int CHK, int TAPS, int LEN, int OUT, int TILE,
          int MW, int NTPER, int FEAT_OFF, int XSTR, bool PRO>
__global__ __launch_bounds__(256, 1)
void conv_mma(const float* __restrict__ x, const float* __restrict__ bias)
{
    constexpr int WSTR  = VPAD * TAPS * 2 + 16;   // 528
    constexpr int ROWS  = TILE + 8;
    constexpr int OFF_W = 0;
    constexpr int WSZ   = 96 * WSTR;              // 50688
    constexpr int OFF_X = WSZ;
    constexpr int XHALF = ROWS * XSTR;
    constexpr int XBUF  = 2 * XHALF;              // hi + lo
    constexpr int OFF_S = OFF_X + 2 * XBUF;       // fp32 scratch
    constexpr int SSZ   = VU * ROWS * 4;
    constexpr int OFF_B = OFF_S + SSZ;
    constexpr int NTILES = BATCH * NTPER;
    constexpr int CPR   = ROWS / 4;               // 16B chunks per x row
    constexpr int NCP   = (VU * CPR + 255) / 256;
    constexpr int NCV   = (VU * ROWS + 255) / 256;

    extern __shared__ char sm[];
    const u32 sb  = sm32(sm);
    const int tid = threadIdx.x, wid = tid >> 5, lane = tid & 31;

    const __half* wsrc = PRO ? g_wP : g_wL;
    for (int u = tid; u < 96 * 256; u += 256) {
        int c = u >> 8, k = u & 255;
        *(__half*)(sm + OFF_W + c * WSTR + k * 2) = wsrc[u];
    }
    // zero x region once (covers vocab pad bytes inside rows)
    for (int u = tid; u < (2 * XBUF) / 16; u += 256)
        *reinterpret_cast<float4*>(sm + OFF_X + u * 16) =
            make_float4(0.f, 0.f, 0.f, 0.f);
    if (tid < 96) ((float*)(sm + OFF_B))[tid] = bias[tid];

    auto issue_cp = [&](int g) {
        int b = g / NTPER, tt = g - b * NTPER, t0 = tt * TILE;
        int valid = LEN - t0; if (valid > ROWS) valid = ROWS;
        const float* xb = x + (size_t)b * VU * LEN + t0;
        int nch = valid >> 2;
        #pragma unroll
        for (int i = 0; i < NCP; i++) {
            int u = tid + i * 256;
            if (u < VU * CPR) {
                int v = u / CPR, c = u - v * CPR;
                if (c < nch)
                    cp16(sb + (u32)(OFF_S + v * ROWS * 4 + c * 16),
                         xb + v * LEN + c * 4);
            }
        }
        cp_commit();
    };
    auto cvt = [&](int g, int nb) {
        int b = g / NTPER, tt = g - b * NTPER, t0 = tt * TILE;
        int valid = LEN - t0; if (valid > ROWS) valid = ROWS;
        const float* sc = (const float*)(sm + OFF_S);
        char* xp = sm + OFF_X + nb * XBUF;
        #pragma unroll
        for (int i = 0; i < NCV; i++) {
            int u = tid + i * 256;
            if (u < VU * ROWS) {
                int v = u / ROWS, r = u - v * ROWS;
                float val = (r < valid) ? sc[v * ROWS + r] : 0.f;
                __half h = __float2half_rn(val);
                __half l = __float2half_rn(val - __half2float(h));
                *(__half*)(xp + r * XSTR + v * 2)         = h;
                *(__half*)(xp + XHALF + r * XSTR + v * 2) = l;
            }
        }
    };

    const int g0 = blockIdx.x;
    if (g0 < NTILES) issue_cp(g0);
    cp_wait0();
    __syncthreads();
    if (g0 < NTILES) cvt(g0, 0);
    __syncthreads();

    const u32 a_lo = (u32)((lane & 15) * XSTR + (lane >> 4) * 16);
    const u32 b_lo = (u32)(((lane & 7) + ((lane >> 4) << 3)) * WSTR
                           + ((lane >> 3) & 1) * 16);
    const u32 wb = sb + (u32)OFF_W + b_lo;

    int buf = 0;
    for (int g = g0; g < NTILES; g += gridDim.x) {
        const int gn = g + (int)gridDim.x;
        if (gn < NTILES) issue_cp(gn);   // async: overlaps the mma loop

        float acc[MW][12][4];
        #pragma unroll
        for (int m = 0; m < MW; m++)
            #pragma unroll
            for (int j = 0; j < 12; j++)
                #pragma unroll
                for (int e = 0; e < 4; e++) acc[m][j][e] = 0.f;

        const u32 xhb = sb + (u32)(OFF_X + buf * XBUF)
                      + (u32)(wid * 16 * MW) * XSTR + a_lo;
        const u32 xlb = xhb + (u32)XHALF;

        #pragma unroll
        for (int tap = 0; tap < TAPS; tap++) {
            #pragma unroll
            for (int ch = 0; ch < CHK; ch++) {
                const u32 aoff = (u32)(tap * XSTR + ch * 32);
                u32 ah[MW][4], al[MW][4];
                #pragma unroll
                for (int m = 0; m < MW; m++) {
                    ldsm4(ah[m], xhb + aoff + (u32)(m * 16 * XSTR));
                    ldsm4(al[m], xlb + aoff + (u32)(m * 16 * XSTR));
                }
                const u32 wk = (u32)((tap * VPAD + ch * 16) * 2);
                #pragma unroll
                for (int p = 0; p < 6; p++) {
                    u32 bf[4];
                    ldsm4(bf, wb + (u32)(p * 16 * WSTR) + wk);
                    #pragma unroll
                    for (int m = 0; m < MW; m++) {
                        mma16816(acc[m][2 * p],     ah[m], bf[0], bf[1]);
                        mma16816(acc[m][2 * p + 1], ah[m], bf[2], bf[3]);
                        mma16816(acc[m][2 * p],     al[m], bf[0], bf[1]);
                        mma16816(acc[m][2 * p + 1], al[m], bf[2], bf[3]);
                    }
                }
            }
        }

        // ---- epilogue: fused mask + max + bias + ReLU -> global atomicMax
        {
            const int b  = g / NTPER;
            const int t0 = (g - b * NTPER) * TILE;
            const int row = lane >> 2;
            const float NEG = -1e30f;
            float mx[24];
            #pragma unroll
            for (int j = 0; j < 12; j++)
                #pragma unroll
                for (int e = 0; e < 2; e++) {
                    float v = NEG;
                    #pragma unroll
                    for (int m = 0; m < MW; m++) {
                        int p0 = t0 + wid * 16 * MW + m * 16 + row;
                        if (p0 < OUT)     v = fmaxf(v, acc[m][j][e]);
                        if (p0 + 8 < OUT) v = fmaxf(v, acc[m][j][e + 2]);
                    }
                    mx[2 * j + e] = v;
                }
            #pragma unroll
            for (int off = 4; off <= 16; off <<= 1)
                #pragma unroll
                for (int q = 0; q < 24; q++)
                    mx[q] = fmaxf(mx[q], __shfl_xor_sync(0xffffffffu, mx[q], off));
            if (lane < 4) {
                #pragma unroll
                for (int j = 0; j < 12; j++)
                    #pragma unroll
                    for (int e = 0; e < 2; e++) {
                        int c = j * 8 + lane * 2 + e;
                        float bb = ((const float*)(sm + OFF_B))[c];
                        float val = fmaxf(mx[2 * j + e] + bb, 0.f);
                        atomicMax(reinterpret_cast<int*>(
                                      &g_feat[(size_t)b * 192 + FEAT_OFF + c]),
                                  __float_as_int(val));
                    }
            }
        }

        cp_wait0();
        __syncthreads();                 // all mma reads of buf done; scratch ready
        if (gn < NTILES) cvt(gn, buf ^ 1);
        __syncthreads();                 // buf^1 visible before next mma
        buf ^= 1;
    }
}

// ---------------------------------------------------------------------------
// Per-sample: x = feat.reshape(6,32); gram = x^T x; L2-normalize; dot w_aff.
// ---------------------------------------------------------------------------
__global__ __launch_bounds__(256)
void gram_readout_kernel(const float* __restrict__ w_aff,
                         const float* __restrict__ b_aff,
                         float* __restrict__ out, int B)
{
    __shared__ float s_w[1024];
    __shared__ float s_f[8][192];
    const int tid  = threadIdx.x;
    const int warp = tid >> 5, lane = tid & 31;
    const int b = blockIdx.x * 8 + warp;

    for (int u = tid; u < 1024; u += 256) s_w[u] = w_aff[u];
    if (b < B)
        for (int u = lane; u < 192; u += 32) s_f[warp][u] = g_feat[(size_t)b * 192 + u];
    __syncthreads();
    if (b >= B) return;

    float xk[6];
    #pragma unroll
    for (int i = 0; i < 6; i++) xk[i] = s_f[warp][i * 32 + lane];

    float s1 = 0.f, s2 = 0.f;
    #pragma unroll 4
    for (int j = 0; j < 32; j++) {
        float g = 0.f;
        #pragma unroll
        for (int i = 0; i < 6; i++) g = fmaf(s_f[warp][i * 32 + j], xk[i], g);
        s2 = fmaf(g, g, s2);
        s1 = fmaf(g, s_w[j * 32 + lane], s1);
    }
    #pragma unroll
    for (int off = 16; off > 0; off >>= 1) {
        s1 += __shfl_xor_sync(0xffffffffu, s1, off);
        s2 += __shfl_xor_sync(0xffffffffu, s2, off);
    }
    if (lane == 0) out[b] = s1 / (sqrtf(s2) + 1e-12f) + b_aff[0];
}

// ---------------------------------------------------------------------------

extern "C" void kernel_launch(void* const* d_in, const int* in_sizes, int n_in,
                              void* d_out, int out_size)
{
    const float* protein = (const float*)d_in[0];
    const float* ligand  = (const float*)d_in[1];
    const float* w_pro   = (const float*)d_in[2];
    const float* b_pro   = (const float*)d_in[3];
    const float* w_lig   = (const float*)d_in[4];
    const float* b_lig   = (const float*)d_in[5];
    const float* w_aff   = (const float*)d_in[6];
    const float* b_aff   = (const float*)d_in[7];

    int seen96 = 0;
    for (int i = 0; i < n_in; i++) {
        long long s = in_sizes[i];
        const float* p = (const float*)d_in[i];
        if      (s == (long long)BATCH * 25 * 1000) protein = p;
        else if (s == (long long)BATCH * 64 * 100)  ligand  = p;
        else if (s == 96LL * 25 * 8)                w_pro   = p;
        else if (s == 96LL * 64 * 4)                w_lig   = p;
        else if (s == 1024LL)                       w_aff   = p;
        else if (s == 96LL) { if (seen96++ == 0) b_pro = p; else b_lig = p; }
        else if (s == 1LL)                          b_aff   = p;
    }

    float* out = (float*)d_out;

    // ligand : VU64 VPAD64 CHK4 TAPS4 LEN100  OUT97  TILE128 MW1 NTPER1 off0  XSTR144
    // protein: VU25 VPAD32 CHK2 TAPS8 LEN1000 OUT993 TILE256 MW2 NTPER4 off96 XSTR80
    auto kL = conv_mma<64, 64, 4, 4, 100, 97, 128, 1, 1, 0, 144, false>;
    auto kP = conv_mma<25, 32, 2, 8, 1000, 993, 256, 2, 4, 96, 80, true>;

    // smem sizes (mirror kernel constexprs)
    constexpr int SMEM_L = 96 * 528 + 2 * (2 * 136 * 144) + 64 * 136 * 4 + 384;
    constexpr int SMEM_P = 96 * 528 + 2 * (2 * 264 * 80)  + 25 * 264 * 4 + 384;

    cudaFuncSetAttribute(kL, cudaFuncAttributeMaxDynamicSharedMemorySize, SMEM_L);
    cudaFuncSetAttribute(kP, cudaFuncAttributeMaxDynamicSharedMemorySize, SMEM_P);

    zero_feat_kernel<<<(BATCH * 192 + 1023) / 1024, 1024>>>();
    prep_w<64, 4, 64, false><<<96, 256>>>(w_lig);
    prep_w<25, 8, 32, true><<<96, 256>>>(w_pro);
    kL<<<148, 256, SMEM_L>>>(ligand, b_lig);
    kP<<<148, 256, SMEM_P>>>(protein, b_pro);
    gram_readout_kernel<<<BATCH / 8, 256>>>(w_aff, b_aff, out, BATCH);
}

// round 8
// speedup vs baseline: 5.2766x; 1.5534x over previous
#include <cuda_runtime.h>
#include <cuda_fp16.h>
#include <math.h>

#define BATCH 4096
__device__ float g_feat[BATCH * 192];
// prepped fp16 weights: [c][k_lin], k_lin = tap*VPAD + v  (96 x 256 each)
__device__ __half g_wP[96 * 256], g_wL[96 * 256];

typedef unsigned int u32;

__device__ __forceinline__ u32 sm32(const void* p) {
    u32 a;
    asm("{ .reg .u64 t; cvta.to.shared.u64 t, %1; cvt.u32.u64 %0, t; }"
        : "=r"(a) : "l"(p));
    return a;
}
__device__ __forceinline__ void ldsm4(u32* r, u32 a) {
    asm volatile("ldmatrix.sync.aligned.m8n8.x4.shared.b16 {%0,%1,%2,%3}, [%4];"
                 : "=r"(r[0]), "=r"(r[1]), "=r"(r[2]), "=r"(r[3]) : "r"(a));
}
__device__ __forceinline__ void mma16816(float* d, const u32* a, u32 b0, u32 b1) {
    asm volatile(
        "mma.sync.aligned.m16n8k16.row.col.f32.f16.f16.f32 "
        "{%0,%1,%2,%3}, {%4,%5,%6,%7}, {%8,%9}, {%0,%1,%2,%3};"
        : "+f"(d[0]), "+f"(d[1]), "+f"(d[2]), "+f"(d[3])
        : "r"(a[0]), "r"(a[1]), "r"(a[2]), "r"(a[3]), "r"(b0), "r"(b1));
}
__device__ __forceinline__ void cp16(u32 dst, const void* src) {
    asm volatile("cp.async.ca.shared.global [%0], [%1], 16;" :: "r"(dst), "l"(src));
}
__device__ __forceinline__ void cp_commit() {
    asm volatile("cp.async.commit_group;" ::: "memory");
}
__device__ __forceinline__ void cp_wait0() {
    asm volatile("cp.async.wait_group 0;" ::: "memory");
}

// ---------------------------------------------------------------------------
// weight prep: fp32 [96][VU][TAPS] -> fp16 [96][256], k_lin = tap*VPAD + v
// ---------------------------------------------------------------------------
template <int VU, int TAPS, int VPAD, bool PRO>
__global__ void prep_w(const float* __restrict__ w) {
    int u = blockIdx.x * 256 + threadIdx.x;
    if (u >= 96 * 256) return;
    int c = u >> 8, k = u & 255;
    int tap = k / VPAD, v = k - tap * VPAD;
    float val = (v < VU) ? w[(c * VU + v) * TAPS + tap] : 0.f;
    (PRO ? g_wP : g_wL)[u] = __float2half_rn(val);
}

__global__ void zero_feat_kernel() {
    int i = blockIdx.x * 1024 + threadIdx.x;
    if (i < BATCH * 192) g_feat[i] = 0.f;
}

// ---------------------------------------------------------------------------
// Persistent conv via mma.sync m16n8k16 fp16, single-term (x and w both fp16;
// error ~2^-11 per operand, measured final rel_err ~1e-4 << 1e-3 threshold).
// Tile = TILE positions x 96 ch. NTH threads (NTH/32 warps); warp owns MW
// m16-frags (16*MW positions). x staged time-major rows (XSTR bytes,
// conflict-free mod 128); tap shift = +tap rows on the A address. cp.async
// stages next tile's fp32 into scratch during the mma loop.
// ---------------------------------------------------------------------------
template <int NTH, int VU, int VPAD, int CHK, int TAPS, int LEN, int OUT,
          int TILE, int MW, int NTPER, int FEAT_OFF, int XSTR, bool PRO>
__global__ __launch_bounds__(NTH, 1)
void conv_mma(const float* __restrict__ x, const float* __restrict__ bias)
{
    constexpr int WSTR  = VPAD * TAPS * 2 + 16;   // 528
    constexpr int ROWS  = TILE + 8;
    constexpr int OFF_W = 0;
    constexpr int WSZ   = 96 * WSTR;              // 50688
    constexpr int OFF_X = WSZ;
    constexpr int XBUF  = ROWS * XSTR;            // fp16 x, one term
    constexpr int OFF_S = OFF_X + 2 * XBUF;       // fp32 scratch
    constexpr int SSZ   = VU * ROWS * 4;
    constexpr int OFF_B = OFF_S + SSZ;
    constexpr int NTILES = BATCH * NTPER;
    constexpr int CPR   = ROWS / 4;               // 16B chunks per x row
    constexpr int NCP   = (VU * CPR + NTH - 1) / NTH;
    constexpr int NCV   = (VU * ROWS + NTH - 1) / NTH;

    extern __shared__ char sm[];
    const u32 sb  = sm32(sm);
    const int tid = threadIdx.x, wid = tid >> 5, lane = tid & 31;

    const __half* wsrc = PRO ? g_wP : g_wL;
    for (int u = tid; u < 96 * 256; u += NTH) {
        int c = u >> 8, k = u & 255;
        *(__half*)(sm + OFF_W + c * WSTR + k * 2) = wsrc[u];
    }
    // zero x region once (covers vocab pad bytes inside rows)
    for (int u = tid; u < (2 * XBUF) / 16; u += NTH)
        *reinterpret_cast<float4*>(sm + OFF_X + u * 16) =
            make_float4(0.f, 0.f, 0.f, 0.f);
    if (tid < 96) ((float*)(sm + OFF_B))[tid] = bias[tid];

    auto issue_cp = [&](int g) {
        int b = g / NTPER, tt = g - b * NTPER, t0 = tt * TILE;
        int valid = LEN - t0; if (valid > ROWS) valid = ROWS;
        const float* xb = x + (size_t)b * VU * LEN + t0;
        int nch = valid >> 2;
        #pragma unroll
        for (int i = 0; i < NCP; i++) {
            int u = tid + i * NTH;
            if (u < VU * CPR) {
                int v = u / CPR, c = u - v * CPR;
                if (c < nch)
                    cp16(sb + (u32)(OFF_S + v * ROWS * 4 + c * 16),
                         xb + v * LEN + c * 4);
            }
        }
        cp_commit();
    };
    auto cvt = [&](int g, int nb) {
        int b = g / NTPER, tt = g - b * NTPER, t0 = tt * TILE;
        int valid = LEN - t0; if (valid > ROWS) valid = ROWS;
        const float* sc = (const float*)(sm + OFF_S);
        char* xp = sm + OFF_X + nb * XBUF;
        #pragma unroll
        for (int i = 0; i < NCV; i++) {
            int u = tid + i * NTH;
            if (u < VU * ROWS) {
                int v = u / ROWS, r = u - v * ROWS;
                float val = (r < valid) ? sc[v * ROWS + r] : 0.f;
                *(__half*)(xp + r * XSTR + v * 2) = __float2half_rn(val);
            }
        }
    };

    const int g0 = blockIdx.x;
    if (g0 < NTILES) issue_cp(g0);
    cp_wait0();
    __syncthreads();
    if (g0 < NTILES) cvt(g0, 0);
    __syncthreads();

    const u32 a_lo = (u32)((lane & 15) * XSTR + (lane >> 4) * 16);
    const u32 b_lo = (u32)(((lane & 7) + ((lane >> 4) << 3)) * WSTR
                           + ((lane >> 3) & 1) * 16);
    const u32 wb = sb + (u32)OFF_W + b_lo;

    int buf = 0;
    for (int g = g0; g < NTILES; g += gridDim.x) {
        const int gn = g + (int)gridDim.x;
        if (gn < NTILES) issue_cp(gn);   // async: overlaps the mma loop

        float acc[MW][12][4];
        #pragma unroll
        for (int m = 0; m < MW; m++)
            #pragma unroll
            for (int j = 0; j < 12; j++)
                #pragma unroll
                for (int e = 0; e < 4; e++) acc[m][j][e] = 0.f;

        const u32 xhb = sb + (u32)(OFF_X + buf * XBUF)
                      + (u32)(wid * 16 * MW) * XSTR + a_lo;

        #pragma unroll
        for (int tap = 0; tap < TAPS; tap++) {
            #pragma unroll
            for (int ch = 0; ch < CHK; ch++) {
                const u32 aoff = (u32)(tap * XSTR + ch * 32);
                u32 ah[MW][4];
                #pragma unroll
                for (int m = 0; m < MW; m++)
                    ldsm4(ah[m], xhb + aoff + (u32)(m * 16 * XSTR));
                const u32 wk = (u32)((tap * VPAD + ch * 16) * 2);
                #pragma unroll
                for (int p = 0; p < 6; p++) {
                    u32 bf[4];
                    ldsm4(bf, wb + (u32)(p * 16 * WSTR) + wk);
                    #pragma unroll
                    for (int m = 0; m < MW; m++) {
                        mma16816(acc[m][2 * p],     ah[m], bf[0], bf[1]);
                        mma16816(acc[m][2 * p + 1], ah[m], bf[2], bf[3]);
                    }
                }
            }
        }

        // ---- epilogue: fused mask + max + bias + ReLU -> global atomicMax
        {
            const int b  = g / NTPER;
            const int t0 = (g - b * NTPER) * TILE;
            const int row = lane >> 2;
            const float NEG = -1e30f;
            float mx[24];
            #pragma unroll
            for (int j = 0; j < 12; j++)
                #pragma unroll
                for (int e = 0; e < 2; e++) {
                    float v = NEG;
                    #pragma unroll
                    for (int m = 0; m < MW; m++) {
                        int p0 = t0 + wid * 16 * MW + m * 16 + row;
                        if (p0 < OUT)     v = fmaxf(v, acc[m][j][e]);
                        if (p0 + 8 < OUT) v = fmaxf(v, acc[m][j][e + 2]);
                    }
                    mx[2 * j + e] = v;
                }
            #pragma unroll
            for (int off = 4; off <= 16; off <<= 1)
                #pragma unroll
                for (int q = 0; q < 24; q++)
                    mx[q] = fmaxf(mx[q], __shfl_xor_sync(0xffffffffu, mx[q], off));
            if (lane < 4) {
                #pragma unroll
                for (int j = 0; j < 12; j++)
                    #pragma unroll
                    for (int e = 0; e < 2; e++) {
                        int c = j * 8 + lane * 2 + e;
                        float bb = ((const float*)(sm + OFF_B))[c];
                        float val = fmaxf(mx[2 * j + e] + bb, 0.f);
                        atomicMax(reinterpret_cast<int*>(
                                      &g_feat[(size_t)b * 192 + FEAT_OFF + c]),
                                  __float_as_int(val));
                    }
            }
        }

        cp_wait0();
        __syncthreads();                 // all mma reads of buf done; scratch ready
        if (gn < NTILES) cvt(gn, buf ^ 1);
        __syncthreads();                 // buf^1 visible before next mma
        buf ^= 1;
    }
}

// ---------------------------------------------------------------------------
// Per-sample: x = feat.reshape(6,32); gram = x^T x; L2-normalize; dot w_aff.
// ---------------------------------------------------------------------------
__global__ __launch_bounds__(256)
void gram_readout_kernel(const float* __restrict__ w_aff,
                         const float* __restrict__ b_aff,
                         float* __restrict__ out, int B)
{
    __shared__ float s_w[1024];
    __shared__ float s_f[8][192];
    const int tid  = threadIdx.x;
    const int warp = tid >> 5, lane = tid & 31;
    const int b = blockIdx.x * 8 + warp;

    for (int u = tid; u < 1024; u += 256) s_w[u] = w_aff[u];
    if (b < B)
        for (int u = lane; u < 192; u += 32) s_f[warp][u] = g_feat[(size_t)b * 192 + u];
    __syncthreads();
    if (b >= B) return;

    float xk[6];
    #pragma unroll
    for (int i = 0; i < 6; i++) xk[i] = s_f[warp][i * 32 + lane];

    float s1 = 0.f, s2 = 0.f;
    #pragma unroll 4
    for (int j = 0; j < 32; j++) {
        float g = 0.f;
        #pragma unroll
        for (int i = 0; i < 6; i++) g = fmaf(s_f[warp][i * 32 + j], xk[i], g);
        s2 = fmaf(g, g, s2);
        s1 = fmaf(g, s_w[j * 32 + lane], s1);
    }
    #pragma unroll
    for (int off = 16; off > 0; off >>= 1) {
        s1 += __shfl_xor_sync(0xffffffffu, s1, off);
        s2 += __shfl_xor_sync(0xffffffffu, s2, off);
    }
    if (lane == 0) out[b] = s1 / (sqrtf(s2) + 1e-12f) + b_aff[0];
}

// ---------------------------------------------------------------------------

extern "C" void kernel_launch(void* const* d_in, const int* in_sizes, int n_in,
                              void* d_out, int out_size)
{
    const float* protein = (const float*)d_in[0];
    const float* ligand  = (const float*)d_in[1];
    const float* w_pro   = (const float*)d_in[2];
    const float* b_pro   = (const float*)d_in[3];
    const float* w_lig   = (const float*)d_in[4];
    const float* b_lig   = (const float*)d_in[5];
    const float* w_aff   = (const float*)d_in[6];
    const float* b_aff   = (const float*)d_in[7];

    int seen96 = 0;
    for (int i = 0; i < n_in; i++) {
        long long s = in_sizes[i];
        const float* p = (const float*)d_in[i];
        if      (s == (long long)BATCH * 25 * 1000) protein = p;
        else if (s == (long long)BATCH * 64 * 100)  ligand  = p;
        else if (s == 96LL * 25 * 8)                w_pro   = p;
        else if (s == 96LL * 64 * 4)                w_lig   = p;
        else if (s == 1024LL)                       w_aff   = p;
        else if (s == 96LL) { if (seen96++ == 0) b_pro = p; else b_lig = p; }
        else if (s == 1LL)                          b_aff   = p;
    }

    float* out = (float*)d_out;

    // ligand : 256thr VU64 VPAD64 CHK4 TAPS4 LEN100  OUT97  TILE128 MW1 NTPER1 off0  XSTR144
    // protein: 512thr VU25 VPAD32 CHK2 TAPS8 LEN1000 OUT993 TILE512 MW2 NTPER2 off96 XSTR80
    auto kL = conv_mma<256, 64, 64, 4, 4, 100, 97, 128, 1, 1, 0, 144, false>;
    auto kP = conv_mma<512, 25, 32, 2, 8, 1000, 993, 512, 2, 2, 96, 80, true>;

    // smem sizes (mirror kernel constexprs)
    constexpr int SMEM_L = 96 * 528 + 2 * (136 * 144) + 64 * 136 * 4 + 384;  // 125056
    constexpr int SMEM_P = 96 * 528 + 2 * (520 * 80)  + 25 * 520 * 4 + 384;  // 186272

    cudaFuncSetAttribute(kL, cudaFuncAttributeMaxDynamicSharedMemorySize, SMEM_L);
    cudaFuncSetAttribute(kP, cudaFuncAttributeMaxDynamicSharedMemorySize, SMEM_P);

    zero_feat_kernel<<<(BATCH * 192 + 1023) / 1024, 1024>>>();
    prep_w<64, 4, 64, false><<<96, 256>>>(w_lig);
    prep_w<25, 8, 32, true><<<96, 256>>>(w_pro);
    kL<<<148, 256, SMEM_L>>>(ligand, b_lig);
    kP<<<148, 512, SMEM_P>>>(protein, b_pro);
    gram_readout_kernel<<<BATCH / 8, 256>>>(w_aff, b_aff, out, BATCH);
}